// round 4
// baseline (speedup 1.0000x reference)
#include <cuda_runtime.h>
#include <cuda_bf16.h>

#define CH 3
#define IH 4096
#define IW 4096
#define TILES 8
#define TSZ 512                 // tile height/width
#define NTILES (CH * TILES * TILES)   // 192
#define AREA (TSZ * TSZ)        // 262144
#define CLIPF 1228.0f           // int(1.2 * 262144 / 256) = 1228

// Scratch (allocation-free rule: __device__ globals, pitfalls.md-sanctioned)
__device__ unsigned char g_v[CH * IH * IW];         // 50.3 MB quantized values
__device__ unsigned int  g_hist[NTILES * 256];      // per-tile histograms
__device__ float         g_lut[NTILES * 256];       // per-tile LUTs

// ---------------------------------------------------------------------------
__global__ void zero_hist_kernel() {
    for (int i = blockIdx.x * blockDim.x + threadIdx.x;
         i < NTILES * 256; i += gridDim.x * blockDim.x)
        g_hist[i] = 0u;
}

// ---------------------------------------------------------------------------
// 1536 blocks: 8 row-chunks (64 rows each) per tile, 192 tiles.
// Each block: 512x64 region = 8192 float4 loads, 256 threads, 32 f4/thread.
__global__ __launch_bounds__(256) void hist_kernel(const float* __restrict__ img) {
    __shared__ unsigned int sh[8][256];     // per-warp sub-histograms
    const int tid  = threadIdx.x;
    const int warp = tid >> 5;

    #pragma unroll
    for (int i = tid; i < 8 * 256; i += 256)
        ((unsigned int*)sh)[i] = 0u;
    __syncthreads();

    const int b     = blockIdx.x;       // 0..1535
    const int chunk = b & 7;
    const int tile  = b >> 3;           // 0..191
    const int c     = tile / (TILES * TILES);
    const int t     = tile % (TILES * TILES);
    const int ty    = t >> 3;
    const int tx    = t & 7;
    const int ybase = ty * TSZ + chunk * 64;
    const int xbase = tx * TSZ;

    for (int i = tid; i < 64 * 128; i += 256) {
        const int y = ybase + (i >> 7);
        const int x = xbase + ((i & 127) << 2);
        const size_t off = ((size_t)c << 24) + ((size_t)y << 12) + (size_t)x;
        const float4 p = *(const float4*)(img + off);
        int v0 = min(max((int)(p.x * 255.0f), 0), 255);
        int v1 = min(max((int)(p.y * 255.0f), 0), 255);
        int v2 = min(max((int)(p.z * 255.0f), 0), 255);
        int v3 = min(max((int)(p.w * 255.0f), 0), 255);
        atomicAdd(&sh[warp][v0], 1u);
        atomicAdd(&sh[warp][v1], 1u);
        atomicAdd(&sh[warp][v2], 1u);
        atomicAdd(&sh[warp][v3], 1u);
        uchar4 u;
        u.x = (unsigned char)v0; u.y = (unsigned char)v1;
        u.z = (unsigned char)v2; u.w = (unsigned char)v3;
        *(uchar4*)(g_v + off) = u;
    }
    __syncthreads();

    unsigned int s = 0;
    #pragma unroll
    for (int w = 0; w < 8; w++) s += sh[w][tid];
    atomicAdd(&g_hist[tile * 256 + tid], s);
}

// ---------------------------------------------------------------------------
// One block per tile, 256 threads (one per bin): clip, redistribute, scan, scale.
__global__ __launch_bounds__(256) void lut_kernel() {
    __shared__ float red[256];
    __shared__ float sc[256];
    const int tile = blockIdx.x;
    const int t    = threadIdx.x;

    const float h  = (float)g_hist[tile * 256 + t];
    float cl       = fminf(h, CLIPF);
    const float ex = h - cl;

    red[t] = ex;
    __syncthreads();
    #pragma unroll
    for (int s = 128; s > 0; s >>= 1) {
        if (t < s) red[t] += red[t + s];
        __syncthreads();
    }
    const float excess = red[0];
    cl += excess * (1.0f / 256.0f);

    // inclusive Hillis-Steele scan (fp32)
    sc[t] = cl;
    __syncthreads();
    #pragma unroll
    for (int off = 1; off < 256; off <<= 1) {
        const float val = (t >= off) ? sc[t - off] : 0.0f;
        __syncthreads();
        sc[t] += val;
        __syncthreads();
    }
    const float cdf = sc[t];
    const float scale = (float)(255.0 / (double)AREA);
    float lut = rintf(cdf * scale);           // round-half-even, matches jnp.round
    lut = fminf(fmaxf(lut, 0.0f), 255.0f);
    g_lut[tile * 256 + t] = lut;
}

// ---------------------------------------------------------------------------
// One thread per float4 (4 pixels along x). Reads u8 scratch, gathers LUT,
// bilinear blend, writes fp32 output.
__global__ __launch_bounds__(256) void apply_kernel(float* __restrict__ out) {
    const int i4 = blockIdx.x * blockDim.x + threadIdx.x;   // 0..12582911
    const size_t p = (size_t)i4 << 2;
    const int c    = (int)(p >> 24);
    const int rem  = (int)(p & 0xFFFFFF);
    const int y    = rem >> 12;
    const int xb   = rem & 0xFFF;

    const float fy = ((float)y + 0.5f) * (1.0f / (float)TSZ) - 0.5f;
    int y0 = (int)floorf(fy);
    y0 = min(max(y0, 0), TILES - 1);
    const float ay = fminf(fmaxf(fy - (float)y0, 0.0f), 1.0f);
    const int y1 = min(y0 + 1, TILES - 1);

    const float* __restrict__ lutr0 = g_lut + (size_t)((c * TILES + y0) * TILES) * 256;
    const float* __restrict__ lutr1 = g_lut + (size_t)((c * TILES + y1) * TILES) * 256;

    const uchar4 u = *(const uchar4*)(g_v + p);
    const unsigned char vv[4] = {u.x, u.y, u.z, u.w};

    float4 o;
    float* op = &o.x;
    #pragma unroll
    for (int e = 0; e < 4; e++) {
        const int x = xb + e;
        const float fx = ((float)x + 0.5f) * (1.0f / (float)TSZ) - 0.5f;
        int x0 = (int)floorf(fx);
        x0 = min(max(x0, 0), TILES - 1);
        const float ax = fminf(fmaxf(fx - (float)x0, 0.0f), 1.0f);
        const int x1 = min(x0 + 1, TILES - 1);
        const int v = (int)vv[e];

        const float g00 = __ldg(lutr0 + x0 * 256 + v);
        const float g01 = __ldg(lutr0 + x1 * 256 + v);
        const float g10 = __ldg(lutr1 + x0 * 256 + v);
        const float g11 = __ldg(lutr1 + x1 * 256 + v);

        const float top = g00 * (1.0f - ax) + g01 * ax;
        const float bot = g10 * (1.0f - ax) + g11 * ax;
        op[e] = (top * (1.0f - ay) + bot * ay) * (1.0f / 255.0f);
    }
    *(float4*)(out + p) = o;
}

// ---------------------------------------------------------------------------
extern "C" void kernel_launch(void* const* d_in, const int* in_sizes, int n_in,
                              void* d_out, int out_size) {
    const float* img = (const float*)d_in[0];
    float* out = (float*)d_out;

    zero_hist_kernel<<<48, 256>>>();
    hist_kernel<<<NTILES * 8, 256>>>(img);
    lut_kernel<<<NTILES, 256>>>();
    apply_kernel<<<(CH * IH * IW / 4 + 255) / 256, 256>>>(out);
}

// round 7
// speedup vs baseline: 1.0461x; 1.0461x over previous
#include <cuda_runtime.h>
#include <cuda_bf16.h>

#define CH 3
#define IH 4096
#define IW 4096
#define TILES 8
#define TSZ 512                 // tile height/width
#define NTILES (CH * TILES * TILES)   // 192
#define AREA (TSZ * TSZ)        // 262144
#define CLIPF 1228.0f           // int(1.2 * 262144 / 256) = 1228

// Scratch (allocation-free rule: __device__ globals)
__device__ unsigned char g_v[CH * IH * IW];         // 50.3 MB quantized values
__device__ unsigned int  g_hist[NTILES * 256];      // per-tile histograms
__device__ float         g_lut[NTILES * 256];       // per-tile LUTs

// ---------------------------------------------------------------------------
__global__ void zero_hist_kernel() {
    for (int i = blockIdx.x * blockDim.x + threadIdx.x;
         i < NTILES * 256; i += gridDim.x * blockDim.x)
        g_hist[i] = 0u;
}

// ---------------------------------------------------------------------------
// 1536 blocks: 8 row-chunks (64 rows each) per tile, 192 tiles.
__global__ __launch_bounds__(256) void hist_kernel(const float* __restrict__ img) {
    __shared__ unsigned int sh[8][256];     // per-warp sub-histograms
    const int tid  = threadIdx.x;
    const int warp = tid >> 5;

    #pragma unroll
    for (int i = tid; i < 8 * 256; i += 256)
        ((unsigned int*)sh)[i] = 0u;
    __syncthreads();

    const int b     = blockIdx.x;       // 0..1535
    const int chunk = b & 7;
    const int tile  = b >> 3;           // 0..191
    const int c     = tile / (TILES * TILES);
    const int t     = tile % (TILES * TILES);
    const int ty    = t >> 3;
    const int tx    = t & 7;
    const int ybase = ty * TSZ + chunk * 64;
    const int xbase = tx * TSZ;

    for (int i = tid; i < 64 * 128; i += 256) {
        const int y = ybase + (i >> 7);
        const int x = xbase + ((i & 127) << 2);
        const size_t off = ((size_t)c << 24) + ((size_t)y << 12) + (size_t)x;
        const float4 p = *(const float4*)(img + off);
        int v0 = min(max((int)(p.x * 255.0f), 0), 255);
        int v1 = min(max((int)(p.y * 255.0f), 0), 255);
        int v2 = min(max((int)(p.z * 255.0f), 0), 255);
        int v3 = min(max((int)(p.w * 255.0f), 0), 255);
        atomicAdd(&sh[warp][v0], 1u);
        atomicAdd(&sh[warp][v1], 1u);
        atomicAdd(&sh[warp][v2], 1u);
        atomicAdd(&sh[warp][v3], 1u);
        uchar4 u;
        u.x = (unsigned char)v0; u.y = (unsigned char)v1;
        u.z = (unsigned char)v2; u.w = (unsigned char)v3;
        *(uchar4*)(g_v + off) = u;
    }
    __syncthreads();

    unsigned int s = 0;
    #pragma unroll
    for (int w = 0; w < 8; w++) s += sh[w][tid];
    atomicAdd(&g_hist[tile * 256 + tid], s);
}

// ---------------------------------------------------------------------------
// One block per tile, 256 threads (one per bin): clip, redistribute, scan, scale.
__global__ __launch_bounds__(256) void lut_kernel() {
    __shared__ float red[256];
    __shared__ float sc[256];
    const int tile = blockIdx.x;
    const int t    = threadIdx.x;

    const float h  = (float)g_hist[tile * 256 + t];
    float cl       = fminf(h, CLIPF);
    const float ex = h - cl;

    red[t] = ex;
    __syncthreads();
    #pragma unroll
    for (int s = 128; s > 0; s >>= 1) {
        if (t < s) red[t] += red[t + s];
        __syncthreads();
    }
    const float excess = red[0];
    cl += excess * (1.0f / 256.0f);

    // inclusive Hillis-Steele scan (fp32)
    sc[t] = cl;
    __syncthreads();
    #pragma unroll
    for (int off = 1; off < 256; off <<= 1) {
        const float val = (t >= off) ? sc[t - off] : 0.0f;
        __syncthreads();
        sc[t] += val;
        __syncthreads();
    }
    const float cdf = sc[t];
    const float scale = (float)(255.0 / (double)AREA);
    float lut = rintf(cdf * scale);           // round-half-even, matches jnp.round
    lut = fminf(fmaxf(lut, 0.0f), 255.0f);
    g_lut[tile * 256 + t] = lut;
}

// ---------------------------------------------------------------------------
// Apply pass, v2 (fixed addressing): per-block y-pre-blended LUT in smem.
// Block = 256 threads × 4 px = 1024 consecutive px of ONE row → base = bi<<10.
// y0/y1/ay constant per block; x-tiles referenced span <=4 columns [c0..c0+3].
// smem Lc[j][v] = ((1-ay)·L[y0,c0+j,v] + ay·L[y1,c0+j,v]) / 255.
// Per pixel: 2 LDS gathers + 1 lerp (was 4 LDG gathers + 3 lerps).
__global__ __launch_bounds__(256) void apply_kernel(float* __restrict__ out) {
    __shared__ float Lc[4][256];

    const int bi   = blockIdx.x;
    const int tid  = threadIdx.x;
    const size_t pbase = (size_t)bi << 10;              // first pixel of block
    const int c    = (int)(pbase >> 24);
    const int rem  = (int)(pbase & 0xFFFFFF);
    const int y    = rem >> 12;
    const int xs   = rem & 0xFFF;                       // block x start (multiple of 1024)

    // y interpolation (block-uniform)
    const float fy = ((float)y + 0.5f) * (1.0f / (float)TSZ) - 0.5f;
    int y0 = (int)floorf(fy);
    y0 = min(max(y0, 0), TILES - 1);
    const float ay = fminf(fmaxf(fy - (float)y0, 0.0f), 1.0f);
    const int y1 = min(y0 + 1, TILES - 1);

    // leftmost referenced x-tile for this block
    const float fxs = ((float)xs + 0.5f) * (1.0f / (float)TSZ) - 0.5f;
    int c0 = (int)floorf(fxs);
    c0 = min(max(c0, 0), TILES - 1);

    // build y-pre-blended LUT columns (folding the final /255)
    const float* __restrict__ base0 = g_lut + (size_t)((c * TILES + y0) * TILES) * 256;
    const float* __restrict__ base1 = g_lut + (size_t)((c * TILES + y1) * TILES) * 256;
    const float w1 = ay * (1.0f / 255.0f);
    const float w0 = (1.0f - ay) * (1.0f / 255.0f);
    #pragma unroll
    for (int j = 0; j < 4; j++) {
        const int col = min(c0 + j, TILES - 1);
        Lc[j][tid] = w0 * __ldg(base0 + col * 256 + tid) + w1 * __ldg(base1 + col * 256 + tid);
    }
    __syncthreads();

    // this thread's 4 pixels
    const size_t p = pbase + ((size_t)tid << 2);
    const uchar4 u = *(const uchar4*)(g_v + p);
    const unsigned char vv[4] = {u.x, u.y, u.z, u.w};
    const int xb = xs + (tid << 2);

    float4 o;
    float* op = &o.x;
    #pragma unroll
    for (int e = 0; e < 4; e++) {
        const int x = xb + e;
        const float fx = ((float)x + 0.5f) * (1.0f / (float)TSZ) - 0.5f;
        int x0 = (int)floorf(fx);
        x0 = min(max(x0, 0), TILES - 1);
        const float ax = fminf(fmaxf(fx - (float)x0, 0.0f), 1.0f);
        const int x1 = min(x0 + 1, TILES - 1);
        const int v = (int)vv[e];
        const float g0 = Lc[x0 - c0][v];
        const float g1 = Lc[x1 - c0][v];
        op[e] = g0 + (g1 - g0) * ax;    // == (1-ax)g0 + ax g1
    }
    *(float4*)(out + p) = o;
}

// ---------------------------------------------------------------------------
extern "C" void kernel_launch(void* const* d_in, const int* in_sizes, int n_in,
                              void* d_out, int out_size) {
    const float* img = (const float*)d_in[0];
    float* out = (float*)d_out;

    zero_hist_kernel<<<48, 256>>>();
    hist_kernel<<<NTILES * 8, 256>>>(img);
    lut_kernel<<<NTILES, 256>>>();
    apply_kernel<<<CH * IH * IW / 1024, 256>>>(out);
}

// round 9
// speedup vs baseline: 1.1321x; 1.0822x over previous
#include <cuda_runtime.h>
#include <cuda_bf16.h>

#define CH 3
#define IH 4096
#define IW 4096
#define TILES 8
#define TSZ 512                 // tile height/width
#define NTILES (CH * TILES * TILES)   // 192
#define AREA (TSZ * TSZ)        // 262144
#define CLIPF 1228.0f           // int(1.2 * 262144 / 256) = 1228

// Scratch (allocation-free rule: __device__ globals)
__device__ unsigned char g_v[CH * IH * IW];         // 50.3 MB quantized values
__device__ unsigned int  g_hist[NTILES * 256];      // per-tile histograms
__device__ float         g_lut[NTILES * 256];       // per-tile LUTs

// ---------------------------------------------------------------------------
__global__ void zero_hist_kernel() {
    for (int i = blockIdx.x * blockDim.x + threadIdx.x;
         i < NTILES * 256; i += gridDim.x * blockDim.x)
        g_hist[i] = 0u;
}

// ---------------------------------------------------------------------------
// 1536 blocks: 8 row-chunks (64 rows each) per tile, 192 tiles.
__global__ __launch_bounds__(256) void hist_kernel(const float* __restrict__ img) {
    __shared__ unsigned int sh[8][256];     // per-warp sub-histograms
    const int tid  = threadIdx.x;
    const int warp = tid >> 5;

    #pragma unroll
    for (int i = tid; i < 8 * 256; i += 256)
        ((unsigned int*)sh)[i] = 0u;
    __syncthreads();

    const int b     = blockIdx.x;       // 0..1535
    const int chunk = b & 7;
    const int tile  = b >> 3;           // 0..191
    const int c     = tile / (TILES * TILES);
    const int t     = tile % (TILES * TILES);
    const int ty    = t >> 3;
    const int tx    = t & 7;
    const int ybase = ty * TSZ + chunk * 64;
    const int xbase = tx * TSZ;

    for (int i = tid; i < 64 * 128; i += 256) {
        const int y = ybase + (i >> 7);
        const int x = xbase + ((i & 127) << 2);
        const size_t off = ((size_t)c << 24) + ((size_t)y << 12) + (size_t)x;
        const float4 p = *(const float4*)(img + off);
        int v0 = min(max((int)(p.x * 255.0f), 0), 255);
        int v1 = min(max((int)(p.y * 255.0f), 0), 255);
        int v2 = min(max((int)(p.z * 255.0f), 0), 255);
        int v3 = min(max((int)(p.w * 255.0f), 0), 255);
        atomicAdd(&sh[warp][v0], 1u);
        atomicAdd(&sh[warp][v1], 1u);
        atomicAdd(&sh[warp][v2], 1u);
        atomicAdd(&sh[warp][v3], 1u);
        uchar4 u;
        u.x = (unsigned char)v0; u.y = (unsigned char)v1;
        u.z = (unsigned char)v2; u.w = (unsigned char)v3;
        *(uchar4*)(g_v + off) = u;
    }
    __syncthreads();

    unsigned int s = 0;
    #pragma unroll
    for (int w = 0; w < 8; w++) s += sh[w][tid];
    atomicAdd(&g_hist[tile * 256 + tid], s);
}

// ---------------------------------------------------------------------------
// One block per tile, 256 threads (one per bin): clip, redistribute, scan, scale.
__global__ __launch_bounds__(256) void lut_kernel() {
    __shared__ float red[256];
    __shared__ float sc[256];
    const int tile = blockIdx.x;
    const int t    = threadIdx.x;

    const float h  = (float)g_hist[tile * 256 + t];
    float cl       = fminf(h, CLIPF);
    const float ex = h - cl;

    red[t] = ex;
    __syncthreads();
    #pragma unroll
    for (int s = 128; s > 0; s >>= 1) {
        if (t < s) red[t] += red[t + s];
        __syncthreads();
    }
    const float excess = red[0];
    cl += excess * (1.0f / 256.0f);

    // inclusive Hillis-Steele scan (fp32)
    sc[t] = cl;
    __syncthreads();
    #pragma unroll
    for (int off = 1; off < 256; off <<= 1) {
        const float val = (t >= off) ? sc[t - off] : 0.0f;
        __syncthreads();
        sc[t] += val;
        __syncthreads();
    }
    const float cdf = sc[t];
    const float scale = (float)(255.0 / (double)AREA);
    float lut = rintf(cdf * scale);           // round-half-even, matches jnp.round
    lut = fminf(fmaxf(lut, 0.0f), 255.0f);
    g_lut[tile * 256 + t] = lut;
}

// ---------------------------------------------------------------------------
// Apply pass, v3: x-tile transitions occur only at x ≡ 0 (mod 8), so within
// an aligned 8-pixel group x0/x1 are constant and ax is affine (and exact in
// fp32: all terms are multiples of 2^-9). Block = 2048 px of one row,
// 8 px/thread. smem float2 pairs Lp[j][v] = (blend(c0+j,v), blend(min(c0+j+1,7),v))
// with y-blend and /255 folded in. Per pixel: byte extract, 1 LDS.64,
// ax = fmax(axb + e/512, 0), 1 lerp. Edge clamps encoded in pairs/fmax.
__global__ __launch_bounds__(256) void apply_kernel(float* __restrict__ out) {
    __shared__ float2 Lp[5][256];

    const int bi   = blockIdx.x;
    const int tid  = threadIdx.x;
    const size_t pbase = (size_t)bi << 11;              // 2048 px per block
    const int c    = (int)(pbase >> 24);
    const int rem  = (int)(pbase & 0xFFFFFF);
    const int y    = rem >> 12;
    const int xs   = rem & 0xFFF;                       // 0 or 2048

    // y interpolation (block-uniform)
    const float fy = ((float)y + 0.5f) * (1.0f / (float)TSZ) - 0.5f;
    int y0 = (int)floorf(fy);
    y0 = min(max(y0, 0), TILES - 1);
    const float ay = fminf(fmaxf(fy - (float)y0, 0.0f), 1.0f);
    const int y1 = min(y0 + 1, TILES - 1);

    const float* __restrict__ base0 = g_lut + (size_t)((c * TILES + y0) * TILES) * 256;
    const float* __restrict__ base1 = g_lut + (size_t)((c * TILES + y1) * TILES) * 256;
    const float w1 = ay * (1.0f / 255.0f);
    const float w0 = (1.0f - ay) * (1.0f / 255.0f);

    // leftmost referenced x-tile for this block
    const float fxs = ((float)xs + 0.5f) * (1.0f / (float)TSZ) - 0.5f;
    const int c0 = max((int)floorf(fxs), 0);

    // build 6 y-pre-blended columns, then 5 adjacent pairs
    float colv[6];
    #pragma unroll
    for (int j = 0; j < 6; j++) {
        const int col = min(c0 + j, TILES - 1);
        colv[j] = w0 * __ldg(base0 + col * 256 + tid) + w1 * __ldg(base1 + col * 256 + tid);
    }
    #pragma unroll
    for (int j = 0; j < 5; j++)
        Lp[j][tid] = make_float2(colv[j], colv[j + 1]);
    __syncthreads();

    // this thread's 8 pixels (aligned-8 group → x0 constant, ax affine)
    const int x = xs + (tid << 3);
    const float fx = ((float)x + 0.5f) * (1.0f / (float)TSZ) - 0.5f;
    int x0 = (int)floorf(fx);
    x0 = min(max(x0, 0), TILES - 1);
    const int j0 = x0 - c0;                             // in [0,4]
    const float axb = fx - (float)x0;                   // <0 only at left edge
    const float2* __restrict__ Lrow = Lp[j0];

    const size_t p = pbase + ((size_t)tid << 3);
    const uint2 u8 = *(const uint2*)(g_v + p);

    float r[8];
    #pragma unroll
    for (int e = 0; e < 8; e++) {
        const unsigned int word = (e < 4) ? u8.x : u8.y;
        const int v = (word >> ((e & 3) * 8)) & 0xFF;
        const float2 g = Lrow[v];
        const float ax = fmaxf(axb + (float)e * (1.0f / (float)TSZ), 0.0f);
        r[e] = g.x + (g.y - g.x) * ax;
    }
    float4* o = (float4*)(out + p);
    o[0] = make_float4(r[0], r[1], r[2], r[3]);
    o[1] = make_float4(r[4], r[5], r[6], r[7]);
}

// ---------------------------------------------------------------------------
extern "C" void kernel_launch(void* const* d_in, const int* in_sizes, int n_in,
                              void* d_out, int out_size) {
    const float* img = (const float*)d_in[0];
    float* out = (float*)d_out;

    zero_hist_kernel<<<48, 256>>>();
    hist_kernel<<<NTILES * 8, 256>>>(img);
    lut_kernel<<<NTILES, 256>>>();
    apply_kernel<<<CH * IH * IW / 2048, 256>>>(out);
}

// round 13
// speedup vs baseline: 1.2556x; 1.1091x over previous
#include <cuda_runtime.h>
#include <cuda_bf16.h>
#include <cuda_fp16.h>

#define CH 3
#define IH 4096
#define IW 4096
#define TILES 8
#define TSZ 512                 // tile height/width
#define NTILES (CH * TILES * TILES)   // 192
#define NCHUNK 8                // row-chunks (blocks) per tile in hist pass
#define AREA (TSZ * TSZ)        // 262144
#define CLIPF 1228.0f           // int(1.2 * 262144 / 256) = 1228

// Scratch (allocation-free rule: __device__ globals)
__device__ unsigned char g_v[CH * IH * IW];            // 50.3 MB quantized values
__device__ unsigned int  g_part[NTILES * NCHUNK * 256]; // per-block partial hists (fully overwritten each run)
__device__ float         g_lut[NTILES * 256];           // per-tile LUTs

// ---------------------------------------------------------------------------
// 1536 blocks: 8 row-chunks (64 rows each) per tile, 192 tiles.
// Each block: 512x64 region, 256 threads. Partial histogram written with
// plain stores (no zeroing kernel, no global atomics needed).
__global__ __launch_bounds__(256) void hist_kernel(const float* __restrict__ img) {
    __shared__ unsigned int sh[8][256];     // per-warp sub-histograms
    const int tid  = threadIdx.x;
    const int warp = tid >> 5;

    #pragma unroll
    for (int i = tid; i < 8 * 256; i += 256)
        ((unsigned int*)sh)[i] = 0u;
    __syncthreads();

    const int b     = blockIdx.x;       // 0..1535
    const int chunk = b & 7;
    const int tile  = b >> 3;           // 0..191
    const int c     = tile / (TILES * TILES);
    const int t     = tile % (TILES * TILES);
    const int ty    = t >> 3;
    const int tx    = t & 7;
    const int ybase = ty * TSZ + chunk * 64;
    const int xbase = tx * TSZ;

    for (int i = tid; i < 64 * 128; i += 256) {
        const int y = ybase + (i >> 7);
        const int x = xbase + ((i & 127) << 2);
        const size_t off = ((size_t)c << 24) + ((size_t)y << 12) + (size_t)x;
        const float4 p = *(const float4*)(img + off);
        int v0 = min(max((int)(p.x * 255.0f), 0), 255);
        int v1 = min(max((int)(p.y * 255.0f), 0), 255);
        int v2 = min(max((int)(p.z * 255.0f), 0), 255);
        int v3 = min(max((int)(p.w * 255.0f), 0), 255);
        atomicAdd(&sh[warp][v0], 1u);
        atomicAdd(&sh[warp][v1], 1u);
        atomicAdd(&sh[warp][v2], 1u);
        atomicAdd(&sh[warp][v3], 1u);
        uchar4 u;
        u.x = (unsigned char)v0; u.y = (unsigned char)v1;
        u.z = (unsigned char)v2; u.w = (unsigned char)v3;
        *(uchar4*)(g_v + off) = u;
    }
    __syncthreads();

    unsigned int s = 0;
    #pragma unroll
    for (int w = 0; w < 8; w++) s += sh[w][tid];
    g_part[b * 256 + tid] = s;          // plain store — no atomics, no pre-zero
}

// ---------------------------------------------------------------------------
// One block per tile, 256 threads (one per bin): sum 8 partials, clip,
// redistribute, scan, scale.
__global__ __launch_bounds__(256) void lut_kernel() {
    __shared__ float red[256];
    __shared__ float sc[256];
    const int tile = blockIdx.x;
    const int t    = threadIdx.x;

    unsigned int hsum = 0;
    #pragma unroll
    for (int k = 0; k < NCHUNK; k++)
        hsum += g_part[(tile * NCHUNK + k) * 256 + t];

    const float h  = (float)hsum;
    float cl       = fminf(h, CLIPF);
    const float ex = h - cl;

    red[t] = ex;
    __syncthreads();
    #pragma unroll
    for (int s = 128; s > 0; s >>= 1) {
        if (t < s) red[t] += red[t + s];
        __syncthreads();
    }
    const float excess = red[0];
    cl += excess * (1.0f / 256.0f);

    // inclusive Hillis-Steele scan (fp32)
    sc[t] = cl;
    __syncthreads();
    #pragma unroll
    for (int off = 1; off < 256; off <<= 1) {
        const float val = (t >= off) ? sc[t - off] : 0.0f;
        __syncthreads();
        sc[t] += val;
        __syncthreads();
    }
    const float cdf = sc[t];
    const float scale = (float)(255.0 / (double)AREA);
    float lut = rintf(cdf * scale);           // round-half-even, matches jnp.round
    lut = fminf(fmaxf(lut, 0.0f), 255.0f);
    g_lut[tile * 256 + t] = lut;
}

// ---------------------------------------------------------------------------
// Apply pass, v4: aligned-8 px groups (x0 constant, ax affine & exact in fp32).
// Per-v pair (g0, g1) stored as __half2 → one LDS.32 per pixel (halves smem
// bytes vs float2, cuts random-v bank-conflict degree ~4.8 → ~3.2).
// fp16 storage error ≤ 2^-11 ≈ 4.9e-4 absolute on [0,1] values, lerp in fp32
// → deterministically under the 1e-3 gate.
__global__ __launch_bounds__(256) void apply_kernel(float* __restrict__ out) {
    __shared__ __half2 Lp[5][256];

    const int bi   = blockIdx.x;
    const int tid  = threadIdx.x;
    const size_t pbase = (size_t)bi << 11;              // 2048 px per block
    const int c    = (int)(pbase >> 24);
    const int rem  = (int)(pbase & 0xFFFFFF);
    const int y    = rem >> 12;
    const int xs   = rem & 0xFFF;                       // 0 or 2048

    // y interpolation (block-uniform)
    const float fy = ((float)y + 0.5f) * (1.0f / (float)TSZ) - 0.5f;
    int y0 = (int)floorf(fy);
    y0 = min(max(y0, 0), TILES - 1);
    const float ay = fminf(fmaxf(fy - (float)y0, 0.0f), 1.0f);
    const int y1 = min(y0 + 1, TILES - 1);

    const float* __restrict__ base0 = g_lut + (size_t)((c * TILES + y0) * TILES) * 256;
    const float* __restrict__ base1 = g_lut + (size_t)((c * TILES + y1) * TILES) * 256;
    const float w1 = ay * (1.0f / 255.0f);
    const float w0 = (1.0f - ay) * (1.0f / 255.0f);

    // leftmost referenced x-tile for this block
    const float fxs = ((float)xs + 0.5f) * (1.0f / (float)TSZ) - 0.5f;
    const int c0 = max((int)floorf(fxs), 0);

    // build 6 y-pre-blended columns, then 5 adjacent half2 pairs
    float colv[6];
    #pragma unroll
    for (int j = 0; j < 6; j++) {
        const int col = min(c0 + j, TILES - 1);
        colv[j] = w0 * __ldg(base0 + col * 256 + tid) + w1 * __ldg(base1 + col * 256 + tid);
    }
    #pragma unroll
    for (int j = 0; j < 5; j++)
        Lp[j][tid] = __floats2half2_rn(colv[j], colv[j + 1]);
    __syncthreads();

    // this thread's 8 pixels (aligned-8 group → x0 constant, ax affine)
    const int x = xs + (tid << 3);
    const float fx = ((float)x + 0.5f) * (1.0f / (float)TSZ) - 0.5f;
    int x0 = (int)floorf(fx);
    x0 = min(max(x0, 0), TILES - 1);
    const int j0 = x0 - c0;                             // in [0,4]
    const float axb = fx - (float)x0;                   // <0 only at left edge
    const __half2* __restrict__ Lrow = Lp[j0];

    const size_t p = pbase + ((size_t)tid << 3);
    const uint2 u8 = *(const uint2*)(g_v + p);

    float r[8];
    #pragma unroll
    for (int e = 0; e < 8; e++) {
        const unsigned int word = (e < 4) ? u8.x : u8.y;
        const int v = (word >> ((e & 3) * 8)) & 0xFF;
        const float2 g = __half22float2(Lrow[v]);
        const float ax = fmaxf(axb + (float)e * (1.0f / (float)TSZ), 0.0f);
        r[e] = g.x + (g.y - g.x) * ax;
    }
    float4* o = (float4*)(out + p);
    o[0] = make_float4(r[0], r[1], r[2], r[3]);
    o[1] = make_float4(r[4], r[5], r[6], r[7]);
}

// ---------------------------------------------------------------------------
extern "C" void kernel_launch(void* const* d_in, const int* in_sizes, int n_in,
                              void* d_out, int out_size) {
    const float* img = (const float*)d_in[0];
    float* out = (float*)d_out;

    hist_kernel<<<NTILES * NCHUNK, 256>>>(img);
    lut_kernel<<<NTILES, 256>>>();
    apply_kernel<<<CH * IH * IW / 2048, 256>>>(out);
}